// round 1
// baseline (speedup 1.0000x reference)
#include <cuda_runtime.h>
#include <cstdint>

// FineMatching: per match m (grid.x):
//   sims[l][s] = dot(x0[m,l,:], x1[m,s,:]) / 128        (64x64x128 GEMM)
//   heatmap    = softmax_l(sims) * softmax_s(sims)
//   argmax over border-masked heatmap -> idx_l, idx_s, biases
//
// Outputs concatenated in d_out (float32):
//   [ heatmap (M*4096) | idx_l (M) | idx_s (M) | biases0 (M*2) | biases1 (M*2) ]

#define NTHREADS 128

// ---- dynamic smem layout (floats) ----
// x0s   : 8192   (64 x 128, row-major, no swizzle: A reads are broadcast)
// x1s   : 8192   (64 x 128, XOR-chunk swizzled)
// sims  : 64*65  (padded to kill row-scan conflicts)
// rm,ri,cm,ci : 64 each
// bv    : 128 floats, bi : 128 ints
#define X0S_OFF   0
#define X1S_OFF   8192
#define SIMS_OFF  (8192 + 8192)
#define RM_OFF    (SIMS_OFF + 64*65)
#define RI_OFF    (RM_OFF + 64)
#define CM_OFF    (RI_OFF + 64)
#define CI_OFF    (CM_OFF + 64)
#define BV_OFF    (CI_OFF + 64)
#define BI_OFF    (BV_OFF + 128)
#define SMEM_FLOATS (BI_OFF + 128)
#define SMEM_BYTES  (SMEM_FLOATS * 4)

__device__ __forceinline__ void ffma2(unsigned long long &d,
                                      unsigned long long a,
                                      unsigned long long b) {
    asm("fma.rn.f32x2 %0, %1, %2, %0;" : "+l"(d) : "l"(a), "l"(b));
}

__device__ __forceinline__ bool inner_mask(int p) {
    int y = p >> 3, x = p & 7;
    return (y >= 1) & (y <= 6) & (x >= 1) & (x <= 6);
}

__global__ void __launch_bounds__(NTHREADS, 2)
fm_kernel(const float* __restrict__ x0, const float* __restrict__ x1,
          float* __restrict__ hm, float* __restrict__ oil,
          float* __restrict__ ois, float* __restrict__ ob0,
          float* __restrict__ ob1) {
    extern __shared__ float smf[];
    float* x0s  = smf + X0S_OFF;
    float* x1s  = smf + X1S_OFF;
    float* sims = smf + SIMS_OFF;
    float* rm   = smf + RM_OFF;
    float* ri   = smf + RI_OFF;
    float* cm   = smf + CM_OFF;
    float* ci   = smf + CI_OFF;
    float* bv   = smf + BV_OFF;
    int*   bi   = (int*)(smf + BI_OFF);

    const int m   = blockIdx.x;
    const int tid = threadIdx.x;

    const float4* p0 = (const float4*)(x0 + (size_t)m * 8192);
    const float4* p1 = (const float4*)(x1 + (size_t)m * 8192);

    // ---- load x0 (plain row-major) + x1 (XOR-chunk swizzled) ----
    float4* x0v = (float4*)x0s;
    float4* x1v = (float4*)x1s;
#pragma unroll
    for (int it = 0; it < 16; it++) {
        int i = tid + it * NTHREADS;           // float4 index, 0..2047
        x0v[i] = p0[i];
        float4 v = p1[i];
        int s = i >> 5;                        // row (0..63)
        int ch = i & 31;                       // 16B chunk within row (0..31)
        int pch = ch ^ ((s >> 2) & 7);         // swizzled chunk
        x1v[s * 32 + pch] = v;
    }
    __syncthreads();

    // ---- GEMM: each thread computes 8 l-rows x 4 s-cols via packed f32x2 ----
    const int tx = tid & 15;                   // -> s block
    const int ty = tid >> 4;                   // -> l block
    const int l0 = ty * 8;
    const int s0 = tx * 4;
    const unsigned swb = (unsigned)((tx & 7) << 4);   // = ((s>>2)&7)<<4 for s in [s0,s0+4)

    unsigned long long acc[8][4];
#pragma unroll
    for (int i = 0; i < 8; i++)
#pragma unroll
        for (int j = 0; j < 4; j++) acc[i][j] = 0ull;

    const char* x0b = (const char*)x0s;
    const char* x1b = (const char*)x1s;

#pragma unroll 2
    for (int kk = 0; kk < 128; kk += 4) {
        unsigned koff = (unsigned)(kk << 2);                 // byte offset in row
        unsigned boff = koff ^ swb;                          // swizzled byte offset
        ulonglong2 b[4];
#pragma unroll
        for (int j = 0; j < 4; j++)
            b[j] = *(const ulonglong2*)(x1b + (s0 + j) * 512 + boff);
        ulonglong2 a[8];
#pragma unroll
        for (int i = 0; i < 8; i++)
            a[i] = *(const ulonglong2*)(x0b + (l0 + i) * 512 + koff);
#pragma unroll
        for (int i = 0; i < 8; i++)
#pragma unroll
            for (int j = 0; j < 4; j++) {
                ffma2(acc[i][j], a[i].x, b[j].x);
                ffma2(acc[i][j], a[i].y, b[j].y);
            }
    }

    const float inv128 = 1.0f / 128.0f;
#pragma unroll
    for (int i = 0; i < 8; i++)
#pragma unroll
        for (int j = 0; j < 4; j++) {
            unsigned long long v = acc[i][j];
            float lo = __uint_as_float((unsigned)v);
            float hi = __uint_as_float((unsigned)(v >> 32));
            sims[(l0 + i) * 65 + (s0 + j)] = (lo + hi) * inv128;
        }
    __syncthreads();

    // ---- row (axis s) and column (axis l) softmax stats ----
    if (tid < 64) {
        int r = tid;
        float mx = -1e30f;
#pragma unroll 4
        for (int k = 0; k < 64; k++) mx = fmaxf(mx, sims[r * 65 + k]);
        float sm = 0.0f;
#pragma unroll 4
        for (int k = 0; k < 64; k++) sm += __expf(sims[r * 65 + k] - mx);
        rm[r] = mx;
        ri[r] = 1.0f / sm;
    } else {
        int c = tid - 64;
        float mx = -1e30f;
#pragma unroll 4
        for (int k = 0; k < 64; k++) mx = fmaxf(mx, sims[k * 65 + c]);
        float sm = 0.0f;
#pragma unroll 4
        for (int k = 0; k < 64; k++) sm += __expf(sims[k * 65 + c] - mx);
        cm[c] = mx;
        ci[c] = 1.0f / sm;
    }
    __syncthreads();

    // ---- fused heatmap write + masked argmax ----
    float bestv = -1.0f;
    int   besti = 0;
    float4* out = (float4*)(hm + (size_t)m * 4096);
#pragma unroll
    for (int it = 0; it < 8; it++) {
        int q = tid + it * NTHREADS;        // float4 index 0..1023
        int l = q >> 4;
        int sb = (q & 15) << 2;
        float rml = rm[l], ril = ri[l];
        bool mL = inner_mask(l);
        float4 hv;
        float* hvp = &hv.x;
#pragma unroll
        for (int u = 0; u < 4; u++) {
            int s = sb + u;
            float sv = sims[l * 65 + s];
            float h = __expf(2.0f * sv - rml - cm[s]) * ril * ci[s];
            hvp[u] = h;
            if (mL && inner_mask(s)) {
                int fidx = (l << 6) | s;
                if (h > bestv || (h == bestv && fidx < besti)) {
                    bestv = h;
                    besti = fidx;
                }
            }
        }
        out[q] = hv;
    }

    // ---- block argmax reduction (min flat index on ties) ----
    bv[tid] = bestv;
    bi[tid] = besti;
    __syncthreads();
#pragma unroll
    for (int off = 64; off > 0; off >>= 1) {
        if (tid < off) {
            float v2 = bv[tid + off];
            int   i2 = bi[tid + off];
            if (v2 > bv[tid] || (v2 == bv[tid] && i2 < bi[tid])) {
                bv[tid] = v2;
                bi[tid] = i2;
            }
        }
        __syncthreads();
    }

    if (tid == 0) {
        int fi = bi[0];
        int il = fi >> 6;
        int is = fi & 63;
        oil[m] = (float)il;
        ois[m] = (float)is;
        // bias table: row idx = y*8+x -> (x - 3.5, y - 3.5)
        ob0[2 * m + 0] = (float)(il & 7) - 3.5f;
        ob0[2 * m + 1] = (float)(il >> 3) - 3.5f;
        ob1[2 * m + 0] = (float)(is & 7) - 3.5f;
        ob1[2 * m + 1] = (float)(is >> 3) - 3.5f;
    }
}

extern "C" void kernel_launch(void* const* d_in, const int* in_sizes, int n_in,
                              void* d_out, int out_size) {
    const float* x0 = (const float*)d_in[0];
    const float* x1 = (const float*)d_in[1];
    const int M = in_sizes[0] / (64 * 128);

    float* out = (float*)d_out;
    float* hm  = out;
    float* oil = hm + (size_t)M * 4096;
    float* ois = oil + M;
    float* ob0 = ois + M;
    float* ob1 = ob0 + 2 * (size_t)M;

    cudaFuncSetAttribute(fm_kernel, cudaFuncAttributeMaxDynamicSharedMemorySize,
                         SMEM_BYTES);
    fm_kernel<<<M, NTHREADS, SMEM_BYTES>>>(x0, x1, hm, oil, ois, ob0, ob1);
}

// round 2
// speedup vs baseline: 1.1887x; 1.1887x over previous
#include <cuda_runtime.h>
#include <cstdint>

// FineMatching: per match m (grid.x):
//   sims[l][s] = dot(x0[m,l,:], x1[m,s,:]) / 128        (64x64x128 GEMM)
//   heatmap    = softmax_l(sims) * softmax_s(sims)
//   masked argmax -> idx_l, idx_s, biases
//
// d_out (float32): [ heatmap (M*4096) | idx_l (M) | idx_s (M) | biases0 (M*2) | biases1 (M*2) ]
//
// This version keeps sims in registers (8x4 tile/thread), does the row softmax
// with 16-lane shuffles, col softmax via a tiny 8x64 smem partial buffer, and
// writes the heatmap directly from registers. smem 67KB -> 3 CTAs/SM.

#define NTHREADS 128

// ---- dynamic smem layout (floats) ----
#define X0S_OFF   0
#define X1S_OFF   8192
#define CPART_OFF (8192 + 8192)       // 8 x 64 partials
#define CMS_OFF   (CPART_OFF + 512)   // 64
#define CIS_OFF   (CMS_OFF + 64)      // 64
#define REDV_OFF  (CIS_OFF + 64)      // 4
#define REDI_OFF  (REDV_OFF + 4)      // 4 (ints)
#define SMEM_FLOATS (REDI_OFF + 4)
#define SMEM_BYTES  (SMEM_FLOATS * 4)

__device__ __forceinline__ void ffma2(unsigned long long &d,
                                      unsigned long long a,
                                      unsigned long long b) {
    asm("fma.rn.f32x2 %0, %1, %2, %0;" : "+l"(d) : "l"(a), "l"(b));
}

__device__ __forceinline__ bool inner_mask(int p) {
    int y = p >> 3, x = p & 7;
    return (y >= 1) & (y <= 6) & (x >= 1) & (x <= 6);
}

__global__ void __launch_bounds__(NTHREADS, 3)
fm_kernel(const float* __restrict__ x0, const float* __restrict__ x1,
          float* __restrict__ hm, float* __restrict__ oil,
          float* __restrict__ ois, float* __restrict__ ob0,
          float* __restrict__ ob1) {
    extern __shared__ float smf[];
    float* x0s   = smf + X0S_OFF;
    float* x1s   = smf + X1S_OFF;
    float* cpart = smf + CPART_OFF;
    float* cms   = smf + CMS_OFF;
    float* cis   = smf + CIS_OFF;
    float* redv  = smf + REDV_OFF;
    int*   redi  = (int*)(smf + REDI_OFF);

    const int m   = blockIdx.x;
    const int tid = threadIdx.x;

    const float4* p0 = (const float4*)(x0 + (size_t)m * 8192);
    const float4* p1 = (const float4*)(x1 + (size_t)m * 8192);

    // ---- load x0 (row-major) + x1 (XOR-chunk swizzled) ----
    float4* x0v = (float4*)x0s;
    float4* x1v = (float4*)x1s;
#pragma unroll
    for (int it = 0; it < 16; it++) {
        int i = tid + it * NTHREADS;           // float4 index 0..2047
        x0v[i] = p0[i];
        float4 v = p1[i];
        int s = i >> 5;
        int ch = i & 31;
        int pch = ch ^ ((s >> 2) & 7);
        x1v[s * 32 + pch] = v;
    }
    __syncthreads();

    // ---- GEMM: 8 l-rows x 4 s-cols per thread, packed f32x2 ----
    const int tx = tid & 15;                   // s block (16-lane group)
    const int ty = tid >> 4;                   // l block
    const int l0 = ty * 8;
    const int s0 = tx * 4;
    const unsigned swb = (unsigned)((tx & 7) << 4);

    unsigned long long acc[8][4];
#pragma unroll
    for (int i = 0; i < 8; i++)
#pragma unroll
        for (int j = 0; j < 4; j++) acc[i][j] = 0ull;

    const char* x0b = (const char*)x0s;
    const char* x1b = (const char*)x1s;

#pragma unroll 2
    for (int kk = 0; kk < 128; kk += 4) {
        unsigned koff = (unsigned)(kk << 2);
        unsigned boff = koff ^ swb;
        ulonglong2 b[4];
#pragma unroll
        for (int j = 0; j < 4; j++)
            b[j] = *(const ulonglong2*)(x1b + (s0 + j) * 512 + boff);
        ulonglong2 a[8];
#pragma unroll
        for (int i = 0; i < 8; i++)
            a[i] = *(const ulonglong2*)(x0b + (l0 + i) * 512 + koff);
#pragma unroll
        for (int i = 0; i < 8; i++)
#pragma unroll
            for (int j = 0; j < 4; j++) {
                ffma2(acc[i][j], a[i].x, b[j].x);
                ffma2(acc[i][j], a[i].y, b[j].y);
            }
    }

    // ---- extract sims tile into registers ----
    const float inv128 = 1.0f / 128.0f;
    float v[8][4];
#pragma unroll
    for (int i = 0; i < 8; i++)
#pragma unroll
        for (int j = 0; j < 4; j++) {
            unsigned long long a = acc[i][j];
            float lo = __uint_as_float((unsigned)a);
            float hi = __uint_as_float((unsigned)(a >> 32));
            v[i][j] = (lo + hi) * inv128;
        }

    // ---- row softmax stats (over s): 16-lane shuffle groups (same ty) ----
    float rmax_[8], rinv_[8];
    float er[8][4];
#pragma unroll
    for (int i = 0; i < 8; i++) {
        float mx = fmaxf(fmaxf(v[i][0], v[i][1]), fmaxf(v[i][2], v[i][3]));
#pragma unroll
        for (int off = 8; off >= 1; off >>= 1)
            mx = fmaxf(mx, __shfl_xor_sync(0xffffffffu, mx, off));
        rmax_[i] = mx;
    }
#pragma unroll
    for (int i = 0; i < 8; i++) {
        float s = 0.0f;
#pragma unroll
        for (int j = 0; j < 4; j++) {
            er[i][j] = __expf(v[i][j] - rmax_[i]);
            s += er[i][j];
        }
#pragma unroll
        for (int off = 8; off >= 1; off >>= 1)
            s += __shfl_xor_sync(0xffffffffu, s, off);
        rinv_[i] = 1.0f / s;
    }

    // ---- col max partials (over l within this thread) ----
    {
        float4 pm;
        float* pmp = &pm.x;
#pragma unroll
        for (int j = 0; j < 4; j++) {
            float mx = v[0][j];
#pragma unroll
            for (int i = 1; i < 8; i++) mx = fmaxf(mx, v[i][j]);
            pmp[j] = mx;
        }
        *(float4*)(cpart + ty * 64 + s0) = pm;
    }
    __syncthreads();
    if (tid < 64) {
        float mx = cpart[tid];
#pragma unroll
        for (int t = 1; t < 8; t++) mx = fmaxf(mx, cpart[t * 64 + tid]);
        cms[tid] = mx;
    }
    __syncthreads();

    // ---- col exp-sums; fold row-normalized part into v (h' = er*ec*rinv) ----
    {
        float4 cm4 = *(const float4*)(cms + s0);
        const float* cmp = &cm4.x;
        float4 ps = make_float4(0.f, 0.f, 0.f, 0.f);
        float* psp = &ps.x;
#pragma unroll
        for (int i = 0; i < 8; i++)
#pragma unroll
            for (int j = 0; j < 4; j++) {
                float ec = __expf(v[i][j] - cmp[j]);
                psp[j] += ec;
                v[i][j] = er[i][j] * ec * rinv_[i];
            }
        *(float4*)(cpart + ty * 64 + s0) = ps;
    }
    __syncthreads();
    if (tid < 64) {
        float s = cpart[tid];
#pragma unroll
        for (int t = 1; t < 8; t++) s += cpart[t * 64 + tid];
        cis[tid] = 1.0f / s;
    }
    __syncthreads();

    // ---- heatmap write from registers + fused masked argmax ----
    float4 ci4 = *(const float4*)(cis + s0);
    const float* cip = &ci4.x;
    bool cmask[4];
#pragma unroll
    for (int j = 0; j < 4; j++) cmask[j] = inner_mask(s0 + j);

    float bestv = -1.0f;
    int   besti = 0;
    float4* out = (float4*)(hm + (size_t)m * 4096);
#pragma unroll
    for (int i = 0; i < 8; i++) {
        int l = l0 + i;
        bool ml = inner_mask(l);
        float4 hv;
        float* hvp = &hv.x;
#pragma unroll
        for (int j = 0; j < 4; j++) {
            float h = v[i][j] * cip[j];
            hvp[j] = h;
            if (ml && cmask[j]) {
                int fidx = (l << 6) | (s0 + j);
                if (h > bestv || (h == bestv && fidx < besti)) {
                    bestv = h;
                    besti = fidx;
                }
            }
        }
        out[l * 16 + tx] = hv;
    }

    // ---- block argmax (min flat index on ties) ----
#pragma unroll
    for (int off = 16; off >= 1; off >>= 1) {
        float ov = __shfl_xor_sync(0xffffffffu, bestv, off);
        int   oi = __shfl_xor_sync(0xffffffffu, besti, off);
        if (ov > bestv || (ov == bestv && oi < besti)) {
            bestv = ov;
            besti = oi;
        }
    }
    if ((tid & 31) == 0) {
        redv[tid >> 5] = bestv;
        redi[tid >> 5] = besti;
    }
    __syncthreads();
    if (tid == 0) {
        float bv = redv[0];
        int   bix = redi[0];
#pragma unroll
        for (int w = 1; w < 4; w++) {
            float ov = redv[w];
            int   oi = redi[w];
            if (ov > bv || (ov == bv && oi < bix)) { bv = ov; bix = oi; }
        }
        int il = bix >> 6;
        int is = bix & 63;
        oil[m] = (float)il;
        ois[m] = (float)is;
        ob0[2 * m + 0] = (float)(il & 7) - 3.5f;
        ob0[2 * m + 1] = (float)(il >> 3) - 3.5f;
        ob1[2 * m + 0] = (float)(is & 7) - 3.5f;
        ob1[2 * m + 1] = (float)(is >> 3) - 3.5f;
    }
}

extern "C" void kernel_launch(void* const* d_in, const int* in_sizes, int n_in,
                              void* d_out, int out_size) {
    const float* x0 = (const float*)d_in[0];
    const float* x1 = (const float*)d_in[1];
    const int M = in_sizes[0] / (64 * 128);

    float* out = (float*)d_out;
    float* hm  = out;
    float* oil = hm + (size_t)M * 4096;
    float* ois = oil + M;
    float* ob0 = ois + M;
    float* ob1 = ob0 + 2 * (size_t)M;

    cudaFuncSetAttribute(fm_kernel, cudaFuncAttributeMaxDynamicSharedMemorySize,
                         SMEM_BYTES);
    fm_kernel<<<M, NTHREADS, SMEM_BYTES>>>(x0, x1, hm, oil, ois, ob0, ob1);
}

// round 3
// speedup vs baseline: 1.2042x; 1.0130x over previous
#include <cuda_runtime.h>
#include <cstdint>

// FineMatching: per match m (grid.x):
//   sims[l][s] = dot(x0[m,l,:], x1[m,s,:]) / 128        (64x64x128 GEMM)
//   heatmap    = softmax_l(sims) * softmax_s(sims)
//   masked argmax -> idx_l, idx_s, biases
//
// d_out (float32): [ heatmap (M*4096) | idx_l (M) | idx_s (M) | biases0 (M*2) | biases1 (M*2) ]
//
// Round-3: x0 (A) read directly from global (broadcast, L1-cached); only x1 (B)
// staged in swizzled smem. smem ~34KB, regs capped 128 -> 4 CTAs/SM (16 warps).

#define NTHREADS 128

// ---- dynamic smem layout (floats) ----
#define X1S_OFF   0
#define CPART_OFF 8192                 // 8 x 64 partials
#define CMS_OFF   (CPART_OFF + 512)    // 64
#define CIS_OFF   (CMS_OFF + 64)       // 64
#define REDV_OFF  (CIS_OFF + 64)       // 4
#define REDI_OFF  (REDV_OFF + 4)       // 4 ints
#define SMEM_FLOATS (REDI_OFF + 4)
#define SMEM_BYTES  (SMEM_FLOATS * 4)

__device__ __forceinline__ void ffma2(unsigned long long &d,
                                      unsigned long long a,
                                      unsigned long long b) {
    asm("fma.rn.f32x2 %0, %1, %2, %0;" : "+l"(d) : "l"(a), "l"(b));
}

__device__ __forceinline__ bool inner_mask(int p) {
    int y = p >> 3, x = p & 7;
    return (y >= 1) & (y <= 6) & (x >= 1) & (x <= 6);
}

__global__ void __launch_bounds__(NTHREADS, 4)
fm_kernel(const float* __restrict__ x0, const float* __restrict__ x1,
          float* __restrict__ hm, float* __restrict__ oil,
          float* __restrict__ ois, float* __restrict__ ob0,
          float* __restrict__ ob1) {
    extern __shared__ float smf[];
    float* x1s   = smf + X1S_OFF;
    float* cpart = smf + CPART_OFF;
    float* cms   = smf + CMS_OFF;
    float* cis   = smf + CIS_OFF;
    float* redv  = smf + REDV_OFF;
    int*   redi  = (int*)(smf + REDI_OFF);

    const int m   = blockIdx.x;
    const int tid = threadIdx.x;

    const float4* p1 = (const float4*)(x1 + (size_t)m * 8192);

    // ---- stage x1 into smem (XOR-chunk swizzled) ----
    float4* x1v = (float4*)x1s;
#pragma unroll
    for (int it = 0; it < 16; it++) {
        int i = tid + it * NTHREADS;           // float4 index 0..2047
        float4 v = p1[i];
        int s = i >> 5;
        int ch = i & 31;
        int pch = ch ^ ((s >> 2) & 7);
        x1v[s * 32 + pch] = v;
    }
    __syncthreads();

    // ---- GEMM: 8 l-rows x 4 s-cols per thread, packed f32x2 ----
    const int tx = tid & 15;                   // s block (16-lane group)
    const int ty = tid >> 4;                   // l block
    const int l0 = ty * 8;
    const int s0 = tx * 4;
    const unsigned swb = (unsigned)((tx & 7) << 4);

    unsigned long long acc[8][4];
#pragma unroll
    for (int i = 0; i < 8; i++)
#pragma unroll
        for (int j = 0; j < 4; j++) acc[i][j] = 0ull;

    const char* x1b = (const char*)x1s;
    const float4* a0 = (const float4*)(x0 + (size_t)m * 8192 + l0 * 128);

#pragma unroll 2
    for (int kk = 0; kk < 32; kk++) {          // kk = k/4
        unsigned boff = ((unsigned)kk << 4) ^ swb;
        ulonglong2 b[4];
#pragma unroll
        for (int j = 0; j < 4; j++)
            b[j] = *(const ulonglong2*)(x1b + (s0 + j) * 512 + boff);
#pragma unroll
        for (int i = 0; i < 8; i++) {
            float4 af = __ldg(a0 + i * 32 + kk);
            unsigned long long axy, azw;
            asm("mov.b64 %0, {%1,%2};" : "=l"(axy) : "f"(af.x), "f"(af.y));
            asm("mov.b64 %0, {%1,%2};" : "=l"(azw) : "f"(af.z), "f"(af.w));
#pragma unroll
            for (int j = 0; j < 4; j++) {
                ffma2(acc[i][j], axy, b[j].x);
                ffma2(acc[i][j], azw, b[j].y);
            }
        }
    }

    // ---- extract sims tile into registers ----
    const float inv128 = 1.0f / 128.0f;
    float v[8][4];
#pragma unroll
    for (int i = 0; i < 8; i++)
#pragma unroll
        for (int j = 0; j < 4; j++) {
            unsigned long long a = acc[i][j];
            float lo = __uint_as_float((unsigned)a);
            float hi = __uint_as_float((unsigned)(a >> 32));
            v[i][j] = (lo + hi) * inv128;
        }

    // ---- row softmax stats (over s): 16-lane shuffle groups ----
    float rmax_[8], rinv_[8];
    float er[8][4];
#pragma unroll
    for (int i = 0; i < 8; i++) {
        float mx = fmaxf(fmaxf(v[i][0], v[i][1]), fmaxf(v[i][2], v[i][3]));
#pragma unroll
        for (int off = 8; off >= 1; off >>= 1)
            mx = fmaxf(mx, __shfl_xor_sync(0xffffffffu, mx, off));
        rmax_[i] = mx;
    }
#pragma unroll
    for (int i = 0; i < 8; i++) {
        float s = 0.0f;
#pragma unroll
        for (int j = 0; j < 4; j++) {
            er[i][j] = __expf(v[i][j] - rmax_[i]);
            s += er[i][j];
        }
#pragma unroll
        for (int off = 8; off >= 1; off >>= 1)
            s += __shfl_xor_sync(0xffffffffu, s, off);
        rinv_[i] = 1.0f / s;
    }

    // ---- col max partials (over l within this thread) ----
    {
        float4 pm;
        float* pmp = &pm.x;
#pragma unroll
        for (int j = 0; j < 4; j++) {
            float mx = v[0][j];
#pragma unroll
            for (int i = 1; i < 8; i++) mx = fmaxf(mx, v[i][j]);
            pmp[j] = mx;
        }
        *(float4*)(cpart + ty * 64 + s0) = pm;
    }
    __syncthreads();
    if (tid < 64) {
        float mx = cpart[tid];
#pragma unroll
        for (int t = 1; t < 8; t++) mx = fmaxf(mx, cpart[t * 64 + tid]);
        cms[tid] = mx;
    }
    __syncthreads();

    // ---- col exp-sums; fold row-normalized part into v ----
    {
        float4 cm4 = *(const float4*)(cms + s0);
        const float* cmp = &cm4.x;
        float4 ps = make_float4(0.f, 0.f, 0.f, 0.f);
        float* psp = &ps.x;
#pragma unroll
        for (int i = 0; i < 8; i++)
#pragma unroll
            for (int j = 0; j < 4; j++) {
                float ec = __expf(v[i][j] - cmp[j]);
                psp[j] += ec;
                v[i][j] = er[i][j] * ec * rinv_[i];
            }
        *(float4*)(cpart + ty * 64 + s0) = ps;
    }
    __syncthreads();
    if (tid < 64) {
        float s = cpart[tid];
#pragma unroll
        for (int t = 1; t < 8; t++) s += cpart[t * 64 + tid];
        cis[tid] = 1.0f / s;
    }
    __syncthreads();

    // ---- heatmap write from registers + fused masked argmax ----
    float4 ci4 = *(const float4*)(cis + s0);
    const float* cip = &ci4.x;
    bool cmask[4];
#pragma unroll
    for (int j = 0; j < 4; j++) cmask[j] = inner_mask(s0 + j);

    float bestv = -1.0f;
    int   besti = 0;
    float4* out = (float4*)(hm + (size_t)m * 4096);
#pragma unroll
    for (int i = 0; i < 8; i++) {
        int l = l0 + i;
        bool ml = inner_mask(l);
        float4 hv;
        float* hvp = &hv.x;
#pragma unroll
        for (int j = 0; j < 4; j++) {
            float h = v[i][j] * cip[j];
            hvp[j] = h;
            if (ml && cmask[j]) {
                int fidx = (l << 6) | (s0 + j);
                if (h > bestv || (h == bestv && fidx < besti)) {
                    bestv = h;
                    besti = fidx;
                }
            }
        }
        out[l * 16 + tx] = hv;
    }

    // ---- block argmax (min flat index on ties) ----
#pragma unroll
    for (int off = 16; off >= 1; off >>= 1) {
        float ov = __shfl_xor_sync(0xffffffffu, bestv, off);
        int   oi = __shfl_xor_sync(0xffffffffu, besti, off);
        if (ov > bestv || (ov == bestv && oi < besti)) {
            bestv = ov;
            besti = oi;
        }
    }
    if ((tid & 31) == 0) {
        redv[tid >> 5] = bestv;
        redi[tid >> 5] = besti;
    }
    __syncthreads();
    if (tid == 0) {
        float bv = redv[0];
        int   bix = redi[0];
#pragma unroll
        for (int w = 1; w < 4; w++) {
            float ov = redv[w];
            int   oi = redi[w];
            if (ov > bv || (ov == bv && oi < bix)) { bv = ov; bix = oi; }
        }
        int il = bix >> 6;
        int is = bix & 63;
        oil[m] = (float)il;
        ois[m] = (float)is;
        ob0[2 * m + 0] = (float)(il & 7) - 3.5f;
        ob0[2 * m + 1] = (float)(il >> 3) - 3.5f;
        ob1[2 * m + 0] = (float)(is & 7) - 3.5f;
        ob1[2 * m + 1] = (float)(is >> 3) - 3.5f;
    }
}

extern "C" void kernel_launch(void* const* d_in, const int* in_sizes, int n_in,
                              void* d_out, int out_size) {
    const float* x0 = (const float*)d_in[0];
    const float* x1 = (const float*)d_in[1];
    const int M = in_sizes[0] / (64 * 128);

    float* out = (float*)d_out;
    float* hm  = out;
    float* oil = hm + (size_t)M * 4096;
    float* ois = oil + M;
    float* ob0 = ois + M;
    float* ob1 = ob0 + 2 * (size_t)M;

    cudaFuncSetAttribute(fm_kernel, cudaFuncAttributeMaxDynamicSharedMemorySize,
                         SMEM_BYTES);
    fm_kernel<<<M, NTHREADS, SMEM_BYTES>>>(x0, x1, hm, oil, ois, ob0, ob1);
}

// round 6
// speedup vs baseline: 1.2171x; 1.0107x over previous
#include <cuda_runtime.h>
#include <cstdint>

// FineMatching: per match m (grid.x):
//   sims[l][s] = dot(x0[m,l,:], x1[m,s,:]) / 128   (64x64x128 GEMM, 3xTF32 mma.sync)
//   heatmap    = softmax_l(sims) * softmax_s(sims)
//   masked argmax -> idx_l, idx_s, biases
//
// d_out (f32): [ heatmap M*4096 | idx_l M | idx_s M | biases0 2M | biases1 2M ]
//
// 3xTF32: operands split hi/lo in registers at fragment load; acc = hi*hi +
// lo*hi + hi*lo -> fp32-level accuracy (~1e-7) with tensor-core throughput.
// A/B raw f32 in XOR-swizzled smem (64KB) -> 3 CTAs/SM.

#define NTHREADS 128

// ---- smem byte offsets ----
#define OFF_A      0                  // 64 rows x 512B, XOR-chunk swizzled
#define OFF_B      32768
#define OFF_SIMS   0                  // overlay on A after GEMM
#define SIMS_PITCH 68
#define OFF_CPART  65536              // 8 x 64 f32
#define OFF_CMS    (OFF_CPART + 2048)
#define OFF_CIS    (OFF_CMS + 256)
#define OFF_REDV   (OFF_CIS + 256)
#define OFF_REDI   (OFF_REDV + 16)
#define SMEM_BYTES (OFF_REDI + 16)

__device__ __forceinline__ uint32_t f2tf32(float f) {
    uint32_t r;
    asm("cvt.rna.tf32.f32 %0, %1;" : "=r"(r) : "f"(f));
    return r;
}

__device__ __forceinline__ void mma_tf32(float& d0, float& d1, float& d2, float& d3,
                                         uint32_t a0, uint32_t a1, uint32_t a2, uint32_t a3,
                                         uint32_t b0, uint32_t b1) {
    asm volatile(
        "mma.sync.aligned.m16n8k8.row.col.f32.tf32.tf32.f32 "
        "{%0,%1,%2,%3}, {%4,%5,%6,%7}, {%8,%9}, {%0,%1,%2,%3};"
        : "+f"(d0), "+f"(d1), "+f"(d2), "+f"(d3)
        : "r"(a0), "r"(a1), "r"(a2), "r"(a3), "r"(b0), "r"(b1));
}

__device__ __forceinline__ bool inner_mask(int p) {
    int y = p >> 3, x = p & 7;
    return (y >= 1) & (y <= 6) & (x >= 1) & (x <= 6);
}

// split f32 -> (hi tf32 bits, lo tf32 bits)
__device__ __forceinline__ void split_tf32(float f, uint32_t& hi, uint32_t& lo) {
    hi = f2tf32(f);
    float r = f - __uint_as_float(hi);
    lo = f2tf32(r);
}

__global__ void __launch_bounds__(NTHREADS, 3)
fm_kernel(const float* __restrict__ x0, const float* __restrict__ x1,
          float* __restrict__ hm, float* __restrict__ oil,
          float* __restrict__ ois, float* __restrict__ ob0,
          float* __restrict__ ob1) {
    extern __shared__ char sm[];
    float* cpart = (float*)(sm + OFF_CPART);
    float* cms   = (float*)(sm + OFF_CMS);
    float* cis   = (float*)(sm + OFF_CIS);
    float* redv  = (float*)(sm + OFF_REDV);
    int*   redi  = (int*)(sm + OFF_REDI);

    const int m    = blockIdx.x;
    const int tid  = threadIdx.x;
    const int warp = tid >> 5;
    const int lane = tid & 31;
    const int g    = lane >> 2;
    const int tig  = lane & 3;

    // ---- stage x0 -> A, x1 -> B (raw f32, XOR-chunk swizzled) ----
    {
        const float4* p0 = (const float4*)(x0 + (size_t)m * 8192);
        const float4* p1 = (const float4*)(x1 + (size_t)m * 8192);
        float4* av = (float4*)(sm + OFF_A);
        float4* bv = (float4*)(sm + OFF_B);
#pragma unroll
        for (int it = 0; it < 16; it++) {
            int i = tid + it * NTHREADS;
            int row = i >> 5;
            int ch  = i & 31;
            int pch = ch ^ (row & 7);
            av[row * 32 + pch] = p0[i];
            bv[row * 32 + pch] = p1[i];
        }
    }
    __syncthreads();

    // ---- GEMM: warp w computes sims[0:64, w*16:(w+1)*16], 3xTF32 ----
    float acc[4][2][4];
#pragma unroll
    for (int mt = 0; mt < 4; mt++)
#pragma unroll
        for (int nt = 0; nt < 2; nt++)
#pragma unroll
            for (int q = 0; q < 4; q++) acc[mt][nt][q] = 0.0f;

    uint32_t abase[4], aswz[4];
#pragma unroll
    for (int mt = 0; mt < 4; mt++) {
        int row = mt * 16 + g;
        abase[mt] = OFF_A + row * 512 + tig * 4;
        aswz[mt]  = (uint32_t)((row & 7) << 4);
    }
    uint32_t bbase[2], bswz[2];
#pragma unroll
    for (int nt = 0; nt < 2; nt++) {
        int row = warp * 16 + nt * 8 + g;
        bbase[nt] = OFF_B + row * 512 + tig * 4;
        bswz[nt]  = (uint32_t)((row & 7) << 4);
    }

#pragma unroll 4
    for (int kt = 0; kt < 16; kt++) {
        uint32_t c0 = (uint32_t)(kt << 5);
        uint32_t c1 = c0 + 16;
        uint32_t bh[2][2], bl[2][2];
#pragma unroll
        for (int nt = 0; nt < 2; nt++) {
            float f0 = *(const float*)(sm + bbase[nt] + (c0 ^ bswz[nt]));
            float f1 = *(const float*)(sm + bbase[nt] + (c1 ^ bswz[nt]));
            split_tf32(f0, bh[nt][0], bl[nt][0]);
            split_tf32(f1, bh[nt][1], bl[nt][1]);
        }
#pragma unroll
        for (int mt = 0; mt < 4; mt++) {
            float f0 = *(const float*)(sm + abase[mt] + (c0 ^ aswz[mt]));
            float f1 = *(const float*)(sm + abase[mt] + 4096 + (c0 ^ aswz[mt]));
            float f2 = *(const float*)(sm + abase[mt] + (c1 ^ aswz[mt]));
            float f3 = *(const float*)(sm + abase[mt] + 4096 + (c1 ^ aswz[mt]));
            uint32_t ah[4], al[4];
            split_tf32(f0, ah[0], al[0]);
            split_tf32(f1, ah[1], al[1]);
            split_tf32(f2, ah[2], al[2]);
            split_tf32(f3, ah[3], al[3]);
#pragma unroll
            for (int nt = 0; nt < 2; nt++) {
                float* d = acc[mt][nt];
                mma_tf32(d[0], d[1], d[2], d[3],
                         al[0], al[1], al[2], al[3], bh[nt][0], bh[nt][1]);
                mma_tf32(d[0], d[1], d[2], d[3],
                         ah[0], ah[1], ah[2], ah[3], bl[nt][0], bl[nt][1]);
                mma_tf32(d[0], d[1], d[2], d[3],
                         ah[0], ah[1], ah[2], ah[3], bh[nt][0], bh[nt][1]);
            }
        }
    }
    __syncthreads();   // done reading A/B; overlay sims

    // ---- write sims to smem (scaled), pitch 68 ----
    {
        float* simsf = (float*)(sm + OFF_SIMS);
        const float inv128 = 1.0f / 128.0f;
#pragma unroll
        for (int mt = 0; mt < 4; mt++) {
            int r0 = mt * 16 + g;
#pragma unroll
            for (int nt = 0; nt < 2; nt++) {
                int c = warp * 16 + nt * 8 + 2 * tig;
                *(float2*)(simsf + r0 * SIMS_PITCH + c) =
                    make_float2(acc[mt][nt][0] * inv128, acc[mt][nt][1] * inv128);
                *(float2*)(simsf + (r0 + 8) * SIMS_PITCH + c) =
                    make_float2(acc[mt][nt][2] * inv128, acc[mt][nt][3] * inv128);
            }
        }
    }
    __syncthreads();

    // ---- epilogue ----
    const int tx = tid & 15;
    const int ty = tid >> 4;
    const int l0 = ty * 8;
    const int s0 = tx * 4;
    const float* simsf = (const float*)(sm + OFF_SIMS);

    float v[8][4];
#pragma unroll
    for (int i = 0; i < 8; i++) {
        float4 t = *(const float4*)(simsf + (l0 + i) * SIMS_PITCH + s0);
        v[i][0] = t.x; v[i][1] = t.y; v[i][2] = t.z; v[i][3] = t.w;
    }

    // row softmax stats (over s): 16-lane shuffle groups
    float rinv_[8];
    float er[8][4];
#pragma unroll
    for (int i = 0; i < 8; i++) {
        float mx = fmaxf(fmaxf(v[i][0], v[i][1]), fmaxf(v[i][2], v[i][3]));
#pragma unroll
        for (int off = 8; off >= 1; off >>= 1)
            mx = fmaxf(mx, __shfl_xor_sync(0xffffffffu, mx, off));
        float s = 0.0f;
#pragma unroll
        for (int j = 0; j < 4; j++) {
            er[i][j] = __expf(v[i][j] - mx);
            s += er[i][j];
        }
#pragma unroll
        for (int off = 8; off >= 1; off >>= 1)
            s += __shfl_xor_sync(0xffffffffu, s, off);
        rinv_[i] = 1.0f / s;
    }

    // col max partials
    {
        float4 pm;
        float* pmp = &pm.x;
#pragma unroll
        for (int j = 0; j < 4; j++) {
            float mx = v[0][j];
#pragma unroll
            for (int i = 1; i < 8; i++) mx = fmaxf(mx, v[i][j]);
            pmp[j] = mx;
        }
        *(float4*)(cpart + ty * 64 + s0) = pm;
    }
    __syncthreads();
    if (tid < 64) {
        float mx = cpart[tid];
#pragma unroll
        for (int t = 1; t < 8; t++) mx = fmaxf(mx, cpart[t * 64 + tid]);
        cms[tid] = mx;
    }
    __syncthreads();

    // col exp-sums; fold row-normalized part into v
    {
        float4 cm4 = *(const float4*)(cms + s0);
        const float* cmp = &cm4.x;
        float4 ps = make_float4(0.f, 0.f, 0.f, 0.f);
        float* psp = &ps.x;
#pragma unroll
        for (int i = 0; i < 8; i++)
#pragma unroll
            for (int j = 0; j < 4; j++) {
                float ec = __expf(v[i][j] - cmp[j]);
                psp[j] += ec;
                v[i][j] = er[i][j] * ec * rinv_[i];
            }
        *(float4*)(cpart + ty * 64 + s0) = ps;
    }
    __syncthreads();
    if (tid < 64) {
        float s = cpart[tid];
#pragma unroll
        for (int t = 1; t < 8; t++) s += cpart[t * 64 + tid];
        cis[tid] = 1.0f / s;
    }
    __syncthreads();

    // heatmap write + fused masked argmax
    float4 ci4 = *(const float4*)(cis + s0);
    const float* cip = &ci4.x;
    bool cmask[4];
#pragma unroll
    for (int j = 0; j < 4; j++) cmask[j] = inner_mask(s0 + j);

    float bestv = -1.0f;
    int   besti = 0;
    float4* out = (float4*)(hm + (size_t)m * 4096);
#pragma unroll
    for (int i = 0; i < 8; i++) {
        int l = l0 + i;
        bool ml = inner_mask(l);
        float4 hv;
        float* hvp = &hv.x;
#pragma unroll
        for (int j = 0; j < 4; j++) {
            float h = v[i][j] * cip[j];
            hvp[j] = h;
            if (ml && cmask[j]) {
                int fidx = (l << 6) | (s0 + j);
                if (h > bestv || (h == bestv && fidx < besti)) {
                    bestv = h;
                    besti = fidx;
                }
            }
        }
        out[l * 16 + tx] = hv;
    }

    // block argmax (min flat index on ties)
#pragma unroll
    for (int off = 16; off >= 1; off >>= 1) {
        float ov = __shfl_xor_sync(0xffffffffu, bestv, off);
        int   oi = __shfl_xor_sync(0xffffffffu, besti, off);
        if (ov > bestv || (ov == bestv && oi < besti)) {
            bestv = ov;
            besti = oi;
        }
    }
    if ((tid & 31) == 0) {
        redv[warp] = bestv;
        redi[warp] = besti;
    }
    __syncthreads();
    if (tid == 0) {
        float bv = redv[0];
        int   bix = redi[0];
#pragma unroll
        for (int w = 1; w < 4; w++) {
            float ov = redv[w];
            int   oi = redi[w];
            if (ov > bv || (ov == bv && oi < bix)) { bv = ov; bix = oi; }
        }
        int il = bix >> 6;
        int is = bix & 63;
        oil[m] = (float)il;
        ois[m] = (float)is;
        ob0[2 * m + 0] = (float)(il & 7) - 3.5f;
        ob0[2 * m + 1] = (float)(il >> 3) - 3.5f;
        ob1[2 * m + 0] = (float)(is & 7) - 3.5f;
        ob1[2 * m + 1] = (float)(is >> 3) - 3.5f;
    }
}

extern "C" void kernel_launch(void* const* d_in, const int* in_sizes, int n_in,
                              void* d_out, int out_size) {
    const float* x0 = (const float*)d_in[0];
    const float* x1 = (const float*)d_in[1];
    const int M = in_sizes[0] / (64 * 128);

    float* out = (float*)d_out;
    float* hm  = out;
    float* oil = hm + (size_t)M * 4096;
    float* ois = oil + M;
    float* ob0 = ois + M;
    float* ob1 = ob0 + 2 * (size_t)M;

    cudaFuncSetAttribute(fm_kernel, cudaFuncAttributeMaxDynamicSharedMemorySize,
                         SMEM_BYTES);
    fm_kernel<<<M, NTHREADS, SMEM_BYTES>>>(x0, x1, hm, oil, ois, ob0, ob1);
}

// round 7
// speedup vs baseline: 1.4109x; 1.1592x over previous
#include <cuda_runtime.h>
#include <cstdint>

// FineMatching: per match m (grid.x):
//   sims[l][s] = dot(x0[m,l,:], x1[m,s,:]) / 128   (64x64x128 GEMM, 3xTF32 mma.sync)
//   heatmap    = softmax_l(sims) * softmax_s(sims)
//   masked argmax -> idx_l, idx_s, biases
//
// d_out (f32): [ heatmap M*4096 | idx_l M | idx_s M | biases0 2M | biases1 2M ]
//
// Round-7: A split hi/lo ONCE at staging into two smem planes, fragments via
// ldmatrix.x4; B raw in smem, split in registers (non-redundant). Epilogue in
// accumulator layout with no-max softmax (32 exps/thread) and direct heatmap
// stores. smem ~98KB -> 2 CTAs/SM.

#define NTHREADS 128

// ---- smem byte offsets ----
#define OFF_AH 0                    // A hi plane, 64 rows x 512B, XOR-swizzled
#define OFF_AL 32768                // A lo plane
#define OFF_B  65536                // B raw f32, swizzled
#define OFF_RP 98304                // row partials: 64 rows x 4 warps f32
#define OFF_RI (OFF_RP + 1024)      // rinv 64 f32
#define OFF_CS (OFF_RI + 256)      // csum 64 f32
#define OFF_CI (OFF_CS + 256)      // cinv 64 f32
#define OFF_RV (OFF_CI + 256)      // 4 f32
#define OFF_RX (OFF_RV + 16)       // 4 i32
#define SMEM_BYTES (OFF_RX + 16)

__device__ __forceinline__ uint32_t smem_u32(const void* p) {
    uint32_t a;
    asm("{ .reg .u64 t; cvta.to.shared.u64 t, %1; cvt.u32.u64 %0, t; }" : "=r"(a) : "l"(p));
    return a;
}

__device__ __forceinline__ uint32_t f2tf32(float f) {
    uint32_t r;
    asm("cvt.rna.tf32.f32 %0, %1;" : "=r"(r) : "f"(f));
    return r;
}

__device__ __forceinline__ void split_tf32(float f, uint32_t& hi, uint32_t& lo) {
    hi = f2tf32(f);
    float r = f - __uint_as_float(hi);
    lo = f2tf32(r);
}

__device__ __forceinline__ void ldsm_x4(uint32_t& r0, uint32_t& r1, uint32_t& r2,
                                        uint32_t& r3, uint32_t addr) {
    asm volatile("ldmatrix.sync.aligned.m8n8.x4.shared.b16 {%0,%1,%2,%3}, [%4];"
                 : "=r"(r0), "=r"(r1), "=r"(r2), "=r"(r3) : "r"(addr));
}

__device__ __forceinline__ void mma_tf32(float& d0, float& d1, float& d2, float& d3,
                                         uint32_t a0, uint32_t a1, uint32_t a2, uint32_t a3,
                                         uint32_t b0, uint32_t b1) {
    asm volatile(
        "mma.sync.aligned.m16n8k8.row.col.f32.tf32.tf32.f32 "
        "{%0,%1,%2,%3}, {%4,%5,%6,%7}, {%8,%9}, {%0,%1,%2,%3};"
        : "+f"(d0), "+f"(d1), "+f"(d2), "+f"(d3)
        : "r"(a0), "r"(a1), "r"(a2), "r"(a3), "r"(b0), "r"(b1));
}

__device__ __forceinline__ bool inner_mask(int p) {
    int y = p >> 3, x = p & 7;
    return (y >= 1) & (y <= 6) & (x >= 1) & (x <= 6);
}

__global__ void __launch_bounds__(NTHREADS, 2)
fm_kernel(const float* __restrict__ x0, const float* __restrict__ x1,
          float* __restrict__ hm, float* __restrict__ oil,
          float* __restrict__ ois, float* __restrict__ ob0,
          float* __restrict__ ob1) {
    extern __shared__ char sm[];
    float* rowpart = (float*)(sm + OFF_RP);
    float* rinv_s  = (float*)(sm + OFF_RI);
    float* csum_s  = (float*)(sm + OFF_CS);
    float* cinv_s  = (float*)(sm + OFF_CI);
    float* redv    = (float*)(sm + OFF_RV);
    int*   redi    = (int*)(sm + OFF_RX);

    const int m    = blockIdx.x;
    const int tid  = threadIdx.x;
    const int warp = tid >> 5;
    const int lane = tid & 31;
    const int g    = lane >> 2;        // group 0..7
    const int tig  = lane & 3;         // thread-in-group

    // ---- stage: A split hi/lo into planes; B raw. XOR-chunk swizzled ----
    {
        const float4* p0 = (const float4*)(x0 + (size_t)m * 8192);
        const float4* p1 = (const float4*)(x1 + (size_t)m * 8192);
        uint4*  ahv = (uint4*)(sm + OFF_AH);
        uint4*  alv = (uint4*)(sm + OFF_AL);
        float4* bv  = (float4*)(sm + OFF_B);
#pragma unroll
        for (int it = 0; it < 16; it++) {
            int i = tid + it * NTHREADS;       // float4 idx 0..2047
            int row = i >> 5;
            int ch  = i & 31;
            int pch = ch ^ (row & 7);
            float4 a4 = p0[i];
            float4 b4 = p1[i];
            uint4 hi4, lo4;
            split_tf32(a4.x, hi4.x, lo4.x);
            split_tf32(a4.y, hi4.y, lo4.y);
            split_tf32(a4.z, hi4.z, lo4.z);
            split_tf32(a4.w, hi4.w, lo4.w);
            ahv[row * 32 + pch] = hi4;
            alv[row * 32 + pch] = lo4;
            bv[row * 32 + pch]  = b4;
        }
    }
    __syncthreads();

    // ---- GEMM: warp w -> sims[0:64, w*16:(w+1)*16], 3xTF32 ----
    float acc[4][2][4];
#pragma unroll
    for (int mt = 0; mt < 4; mt++)
#pragma unroll
        for (int nt = 0; nt < 2; nt++)
#pragma unroll
            for (int qq = 0; qq < 4; qq++) acc[mt][nt][qq] = 0.0f;

    const uint32_t smb = smem_u32(sm);

    // ldmatrix lane addressing for A
    const int qm = lane >> 3;           // matrix id 0..3
    const int rm = lane & 7;            // row within matrix
    const uint32_t kq = (uint32_t)((qm >> 1) << 4);
    uint32_t abase[4], axm[4];
#pragma unroll
    for (int mt = 0; mt < 4; mt++) {
        int row = mt * 16 + ((qm & 1) << 3) + rm;
        abase[mt] = smb + OFF_AH + row * 512;
        axm[mt]   = (uint32_t)((row & 7) << 4);
    }
    // B addressing (scalar LDS per fragment)
    uint32_t bbase[2], bswz[2];
#pragma unroll
    for (int nt = 0; nt < 2; nt++) {
        int row = warp * 16 + nt * 8 + g;
        bbase[nt] = OFF_B + row * 512 + tig * 4;
        bswz[nt]  = (uint32_t)((row & 7) << 4);
    }

#pragma unroll 4
    for (int kt = 0; kt < 16; kt++) {
        uint32_t c0 = (uint32_t)(kt << 5);
        uint32_t c1 = c0 + 16;
        uint32_t koff = c0 | kq;
        // B fragments: load raw f32, split in registers (non-redundant)
        uint32_t bh[2][2], bl[2][2];
#pragma unroll
        for (int nt = 0; nt < 2; nt++) {
            float f0 = *(const float*)(sm + bbase[nt] + (c0 ^ bswz[nt]));
            float f1 = *(const float*)(sm + bbase[nt] + (c1 ^ bswz[nt]));
            split_tf32(f0, bh[nt][0], bl[nt][0]);
            split_tf32(f1, bh[nt][1], bl[nt][1]);
        }
#pragma unroll
        for (int mt = 0; mt < 4; mt++) {
            uint32_t ad = abase[mt] + (koff ^ axm[mt]);
            uint32_t ah0, ah1, ah2, ah3, al0, al1, al2, al3;
            ldsm_x4(ah0, ah1, ah2, ah3, ad);
            ldsm_x4(al0, al1, al2, al3, ad + 32768);
#pragma unroll
            for (int nt = 0; nt < 2; nt++) {
                float* d = acc[mt][nt];
                mma_tf32(d[0], d[1], d[2], d[3],
                         al0, al1, al2, al3, bh[nt][0], bh[nt][1]);
                mma_tf32(d[0], d[1], d[2], d[3],
                         ah0, ah1, ah2, ah3, bl[nt][0], bl[nt][1]);
                mma_tf32(d[0], d[1], d[2], d[3],
                         ah0, ah1, ah2, ah3, bh[nt][0], bh[nt][1]);
            }
        }
    }

    // ---- epilogue in accumulator layout ----
    // acc[mt][nt][0]: (row=mt*16+g,   col=warp*16+nt*8+2tig)
    // acc[mt][nt][1]: (row,           col+1)
    // acc[mt][nt][2]: (row+8,         col)
    // acc[mt][nt][3]: (row+8,         col+1)
    const float inv128 = 1.0f / 128.0f;
    // e = exp(sims) — no max subtraction (sims in ±~0.5)
#pragma unroll
    for (int mt = 0; mt < 4; mt++)
#pragma unroll
        for (int nt = 0; nt < 2; nt++)
#pragma unroll
            for (int qq = 0; qq < 4; qq++)
                acc[mt][nt][qq] = __expf(acc[mt][nt][qq] * inv128);

    // row partial sums (this warp's 16 cols) -> rowpart[row*4 + warp]
#pragma unroll
    for (int mt = 0; mt < 4; mt++) {
        float r0 = acc[mt][0][0] + acc[mt][0][1] + acc[mt][1][0] + acc[mt][1][1];
        float r1 = acc[mt][0][2] + acc[mt][0][3] + acc[mt][1][2] + acc[mt][1][3];
        r0 += __shfl_xor_sync(0xffffffffu, r0, 1);
        r0 += __shfl_xor_sync(0xffffffffu, r0, 2);
        r1 += __shfl_xor_sync(0xffffffffu, r1, 1);
        r1 += __shfl_xor_sync(0xffffffffu, r1, 2);
        if (tig == 0) {
            rowpart[(mt * 16 + g) * 4 + warp]     = r0;
            rowpart[(mt * 16 + g + 8) * 4 + warp] = r1;
        }
    }
    // col sums (all 64 rows, in-warp) -> csum[col]
#pragma unroll
    for (int nt = 0; nt < 2; nt++) {
        float c0 = acc[0][nt][0] + acc[0][nt][2];
        float c1 = acc[0][nt][1] + acc[0][nt][3];
#pragma unroll
        for (int mt = 1; mt < 4; mt++) {
            c0 += acc[mt][nt][0] + acc[mt][nt][2];
            c1 += acc[mt][nt][1] + acc[mt][nt][3];
        }
        c0 += __shfl_xor_sync(0xffffffffu, c0, 4);
        c0 += __shfl_xor_sync(0xffffffffu, c0, 8);
        c0 += __shfl_xor_sync(0xffffffffu, c0, 16);
        c1 += __shfl_xor_sync(0xffffffffu, c1, 4);
        c1 += __shfl_xor_sync(0xffffffffu, c1, 8);
        c1 += __shfl_xor_sync(0xffffffffu, c1, 16);
        if (g == 0)
            *(float2*)(csum_s + warp * 16 + nt * 8 + 2 * tig) = make_float2(c0, c1);
    }
    __syncthreads();
    if (tid < 64) {
        const float* rp = rowpart + tid * 4;
        rinv_s[tid] = 1.0f / (rp[0] + rp[1] + rp[2] + rp[3]);
    } else {
        int c = tid - 64;
        cinv_s[c] = 1.0f / csum_s[c];
    }
    __syncthreads();

    // h-pass: h = e*e*rinv[row]*cinv[col]; store + masked argmax
    float rin[4][2];
#pragma unroll
    for (int mt = 0; mt < 4; mt++) {
        rin[mt][0] = rinv_s[mt * 16 + g];
        rin[mt][1] = rinv_s[mt * 16 + g + 8];
    }
    float2 cin[2];
#pragma unroll
    for (int nt = 0; nt < 2; nt++)
        cin[nt] = *(const float2*)(cinv_s + warp * 16 + nt * 8 + 2 * tig);

    bool mrow[4][2];
#pragma unroll
    for (int mt = 0; mt < 4; mt++) {
        mrow[mt][0] = inner_mask(mt * 16 + g);
        mrow[mt][1] = inner_mask(mt * 16 + g + 8);
    }
    bool mcol[2][2];
#pragma unroll
    for (int nt = 0; nt < 2; nt++) {
        int c = warp * 16 + nt * 8 + 2 * tig;
        mcol[nt][0] = inner_mask(c);
        mcol[nt][1] = inner_mask(c + 1);
    }

    float bestv = -1.0f;
    int   besti = 0;
    float* hmbase = hm + (size_t)m * 4096;
#pragma unroll
    for (int mt = 0; mt < 4; mt++) {
#pragma unroll
        for (int nt = 0; nt < 2; nt++) {
            int row0 = mt * 16 + g;
            int col0 = warp * 16 + nt * 8 + 2 * tig;
            float h0 = acc[mt][nt][0] * acc[mt][nt][0] * rin[mt][0] * cin[nt].x;
            float h1 = acc[mt][nt][1] * acc[mt][nt][1] * rin[mt][0] * cin[nt].y;
            float h2 = acc[mt][nt][2] * acc[mt][nt][2] * rin[mt][1] * cin[nt].x;
            float h3 = acc[mt][nt][3] * acc[mt][nt][3] * rin[mt][1] * cin[nt].y;
            *(float2*)(hmbase + row0 * 64 + col0)       = make_float2(h0, h1);
            *(float2*)(hmbase + (row0 + 8) * 64 + col0) = make_float2(h2, h3);
            if (mrow[mt][0]) {
                if (mcol[nt][0]) {
                    int fi = (row0 << 6) | col0;
                    if (h0 > bestv || (h0 == bestv && fi < besti)) { bestv = h0; besti = fi; }
                }
                if (mcol[nt][1]) {
                    int fi = (row0 << 6) | (col0 + 1);
                    if (h1 > bestv || (h1 == bestv && fi < besti)) { bestv = h1; besti = fi; }
                }
            }
            if (mrow[mt][1]) {
                if (mcol[nt][0]) {
                    int fi = ((row0 + 8) << 6) | col0;
                    if (h2 > bestv || (h2 == bestv && fi < besti)) { bestv = h2; besti = fi; }
                }
                if (mcol[nt][1]) {
                    int fi = ((row0 + 8) << 6) | (col0 + 1);
                    if (h3 > bestv || (h3 == bestv && fi < besti)) { bestv = h3; besti = fi; }
                }
            }
        }
    }

    // warp argmax reduce (min flat idx on ties)
#pragma unroll
    for (int off = 16; off >= 1; off >>= 1) {
        float ov = __shfl_xor_sync(0xffffffffu, bestv, off);
        int   oi = __shfl_xor_sync(0xffffffffu, besti, off);
        if (ov > bestv || (ov == bestv && oi < besti)) { bestv = ov; besti = oi; }
    }
    if (lane == 0) { redv[warp] = bestv; redi[warp] = besti; }
    __syncthreads();
    if (tid == 0) {
        float bv = redv[0];
        int   bx = redi[0];
#pragma unroll
        for (int w = 1; w < 4; w++) {
            float ov = redv[w];
            int   oi = redi[w];
            if (ov > bv || (ov == bv && oi < bx)) { bv = ov; bx = oi; }
        }
        int il = bx >> 6;
        int is = bx & 63;
        oil[m] = (float)il;
        ois[m] = (float)is;
        ob0[2 * m + 0] = (float)(il & 7) - 3.5f;
        ob0[2 * m + 1] = (float)(il >> 3) - 3.5f;
        ob1[2 * m + 0] = (float)(is & 7) - 3.5f;
        ob1[2 * m + 1] = (float)(is >> 3) - 3.5f;
    }
}

extern "C" void kernel_launch(void* const* d_in, const int* in_sizes, int n_in,
                              void* d_out, int out_size) {
    const float* x0 = (const float*)d_in[0];
    const float* x1 = (const float*)d_in[1];
    const int M = in_sizes[0] / (64 * 128);

    float* out = (float*)d_out;
    float* hm  = out;
    float* oil = hm + (size_t)M * 4096;
    float* ois = oil + M;
    float* ob0 = ois + M;
    float* ob1 = ob0 + 2 * (size_t)M;

    cudaFuncSetAttribute(fm_kernel, cudaFuncAttributeMaxDynamicSharedMemorySize,
                         SMEM_BYTES);
    fm_kernel<<<M, NTHREADS, SMEM_BYTES>>>(x0, x1, hm, oil, ois, ob0, ob1);
}